// round 16
// baseline (speedup 1.0000x reference)
#include <cuda_runtime.h>
#include <cuda_fp16.h>
#include <cstdint>

#define NB 4
#define NT 1024
#define ND 512
#define NH 8
#define NHD 64
#define NHDIM 512   // NH*NHD
#define NM 4096     // NB*NT

// ---------------- scratch (static device arrays; no allocation) ----------------
__device__ float  g_q [NB*NH*NT*NHD];                // [b,h,t,d]   8 MB
__device__ float  g_k [NB*NH*NT*NHD];
__device__ __half g_vh[NB*NH*NT*NHD];                // V fp16, 4 MB
__device__ __half g_S [(size_t)NB*NH*NT*NT];         // raw scaled scores, fp16, 64 MB
__device__ __half g_Pf[(size_t)NB*NH*NT*NT];         // masked-normalized P (fwd), fp16
__device__ __half g_Pr[(size_t)NB*NH*NT*NT];         // masked-normalized P (rev), fp16
__device__ __half g_Tf[NM*NHDIM];                    // [b*t, h*64+d]  fp16, 4 MB
__device__ __half g_Tr[NM*NHDIM];
__device__ float  g_FG[4*(size_t)NM*NHDIM];          // Ff|Gf|Fr|Gr pre-act, 32 MB

// ======================= mma helpers ================================
__device__ __forceinline__ uint32_t f2tf(float f){
    uint32_t r; asm("cvt.rna.tf32.f32 %0, %1;" : "=r"(r) : "f"(f)); return r;
}
__device__ __forceinline__ void mma_tf32(float* c, const uint32_t* a, const uint32_t* b){
    asm volatile("mma.sync.aligned.m16n8k8.row.col.f32.tf32.tf32.f32 "
        "{%0,%1,%2,%3}, {%4,%5,%6,%7}, {%8,%9}, {%0,%1,%2,%3};"
        : "+f"(c[0]), "+f"(c[1]), "+f"(c[2]), "+f"(c[3])
        : "r"(a[0]), "r"(a[1]), "r"(a[2]), "r"(a[3]), "r"(b[0]), "r"(b[1]));
}
__device__ __forceinline__ void mma_f16(float* c, const uint32_t* a, const uint32_t* b){
    asm volatile("mma.sync.aligned.m16n8k16.row.col.f32.f16.f16.f32 "
        "{%0,%1,%2,%3}, {%4,%5,%6,%7}, {%8,%9}, {%0,%1,%2,%3};"
        : "+f"(c[0]), "+f"(c[1]), "+f"(c[2]), "+f"(c[3])
        : "r"(a[0]), "r"(a[1]), "r"(a[2]), "r"(a[3]), "r"(b[0]), "r"(b[1]));
}

#define PA 36    // fp32 row pad: frag bank = 4g+t -> conflict-free
#define PB 136
#define PH 40    // fp16 row pad (halves): 16B-aligned rows + conflict-free frags

// Mainloop (fp32 A): acc += A[m0.., k] * W[k, n0..]^T, K=512, both stride 512.
__device__ __forceinline__ void mma_mainloop(const float* __restrict__ A, int m0,
                                             const float* __restrict__ W, int n0,
                                             float (*sA)[PA], float (*sB)[PB],
                                             float acc[4][4][4],
                                             int tid, int g, int t, int wm, int wn)
{
    for (int c=0; c<16; c++){
#pragma unroll
        for (int i=0;i<4;i++){
            int f = i*256 + tid;
            int r = f>>3, c4 = f&7;
            float4 v = *(const float4*)&A[(size_t)(m0+r)*512 + c*32 + c4*4];
            uint32_t* pa = (uint32_t*)&sA[r][c4*4];
            pa[0]=f2tf(v.x); pa[1]=f2tf(v.y); pa[2]=f2tf(v.z); pa[3]=f2tf(v.w);
        }
#pragma unroll
        for (int i=0;i<4;i++){
            int f = i*256 + tid;
            int kl = f>>5, n4 = f&31;
            float4 v = *(const float4*)&W[(size_t)(c*32+kl)*512 + n0 + n4*4];
            uint32_t* pb = (uint32_t*)&sB[kl][n4*4];
            pb[0]=f2tf(v.x); pb[1]=f2tf(v.y); pb[2]=f2tf(v.z); pb[3]=f2tf(v.w);
        }
        __syncthreads();
#pragma unroll
        for (int kk=0; kk<4; kk++){
            const int k8 = kk*8;
            uint32_t afr[4][4];
#pragma unroll
            for (int mi=0; mi<4; mi++){
                int rb = wm*64 + mi*16;
                afr[mi][0] = __float_as_uint(sA[rb+g  ][k8+t  ]);
                afr[mi][1] = __float_as_uint(sA[rb+g+8][k8+t  ]);
                afr[mi][2] = __float_as_uint(sA[rb+g  ][k8+t+4]);
                afr[mi][3] = __float_as_uint(sA[rb+g+8][k8+t+4]);
            }
            uint32_t bfr[4][2];
#pragma unroll
            for (int ni=0; ni<4; ni++){
                int nb = wn*32 + ni*8 + g;
                bfr[ni][0] = __float_as_uint(sB[k8+t  ][nb]);
                bfr[ni][1] = __float_as_uint(sB[k8+t+4][nb]);
            }
#pragma unroll
            for (int mi=0; mi<4; mi++)
#pragma unroll
                for (int ni=0; ni<4; ni++)
                    mma_tf32(acc[mi][ni], afr[mi], bfr[ni]);
        }
        __syncthreads();
    }
}

// Mainloop (fp16 A): same but A is __half with stride 512.
__device__ __forceinline__ void mma_mainloop_h(const __half* __restrict__ A, int m0,
                                               const float* __restrict__ W, int n0,
                                               float (*sA)[PA], float (*sB)[PB],
                                               float acc[4][4][4],
                                               int tid, int g, int t, int wm, int wn)
{
    for (int c=0; c<16; c++){
#pragma unroll
        for (int i=0;i<2;i++){
            int f = i*256 + tid;
            int r = f>>2, k8 = f&3;
            uint4 v = *(const uint4*)&A[(size_t)(m0+r)*512 + c*32 + k8*8];
            const __half2* hv = (const __half2*)&v;
            float2 f0=__half22float2(hv[0]), f1=__half22float2(hv[1]);
            float2 f2=__half22float2(hv[2]), f3=__half22float2(hv[3]);
            uint32_t* pa = (uint32_t*)&sA[r][k8*8];
            pa[0]=f2tf(f0.x); pa[1]=f2tf(f0.y); pa[2]=f2tf(f1.x); pa[3]=f2tf(f1.y);
            pa[4]=f2tf(f2.x); pa[5]=f2tf(f2.y); pa[6]=f2tf(f3.x); pa[7]=f2tf(f3.y);
        }
#pragma unroll
        for (int i=0;i<4;i++){
            int f = i*256 + tid;
            int kl = f>>5, n4 = f&31;
            float4 v = *(const float4*)&W[(size_t)(c*32+kl)*512 + n0 + n4*4];
            uint32_t* pb = (uint32_t*)&sB[kl][n4*4];
            pb[0]=f2tf(v.x); pb[1]=f2tf(v.y); pb[2]=f2tf(v.z); pb[3]=f2tf(v.w);
        }
        __syncthreads();
#pragma unroll
        for (int kk=0; kk<4; kk++){
            const int k8 = kk*8;
            uint32_t afr[4][4];
#pragma unroll
            for (int mi=0; mi<4; mi++){
                int rb = wm*64 + mi*16;
                afr[mi][0] = __float_as_uint(sA[rb+g  ][k8+t  ]);
                afr[mi][1] = __float_as_uint(sA[rb+g+8][k8+t  ]);
                afr[mi][2] = __float_as_uint(sA[rb+g  ][k8+t+4]);
                afr[mi][3] = __float_as_uint(sA[rb+g+8][k8+t+4]);
            }
            uint32_t bfr[4][2];
#pragma unroll
            for (int ni=0; ni<4; ni++){
                int nb = wn*32 + ni*8 + g;
                bfr[ni][0] = __float_as_uint(sB[k8+t  ][nb]);
                bfr[ni][1] = __float_as_uint(sB[k8+t+4][nb]);
            }
#pragma unroll
            for (int mi=0; mi<4; mi++)
#pragma unroll
                for (int ni=0; ni<4; ni++)
                    mma_tf32(acc[mi][ni], afr[mi], bfr[ni]);
        }
        __syncthreads();
    }
}

// ---------------- K1: QKV projection, tf32 mma (V emitted fp16) ---------------
__global__ __launch_bounds__(256) void k_proj_mma(const float* __restrict__ X,
                                                  const float* __restrict__ Wq,
                                                  const float* __restrict__ bq,
                                                  const float* __restrict__ Wk,
                                                  const float* __restrict__ bk,
                                                  const float* __restrict__ Wv,
                                                  const float* __restrict__ bv)
{
    __shared__ float sA[128][PA];
    __shared__ float sB[32][PB];
    const int tid = threadIdx.x, lane = tid&31, warp = tid>>5;
    const int g = lane>>2, t = lane&3;
    const int wm = warp>>2, wn = warp&3;
    const int n0 = blockIdx.x*128, m0 = blockIdx.y*128;
    const int mat = n0>>9, col0 = n0&511;
    const float* W    = (mat==0)?Wq:(mat==1)?Wk:Wv;
    const float* bias = (mat==0)?bq:(mat==1)?bk:bv;

    float acc[4][4][4];
#pragma unroll
    for (int mi=0;mi<4;mi++)
#pragma unroll
        for (int ni=0;ni<4;ni++)
#pragma unroll
            for (int r=0;r<4;r++) acc[mi][ni][r]=0.f;

    mma_mainloop(X, m0, W, col0, sA, sB, acc, tid, g, t, wm, wn);

#pragma unroll
    for (int mi=0;mi<4;mi++){
#pragma unroll
        for (int ni=0;ni<4;ni++){
            int colb = col0 + wn*32 + ni*8 + 2*t;
            int h = colb>>6, d = colb&63;
            float b0v = bias[colb], b1v = bias[colb+1];
            int r0 = m0 + wm*64 + mi*16 + g;
#pragma unroll
            for (int half=0; half<2; half++){
                int m = r0 + half*8;
                int b = m>>10, tt = m&1023;
                float ox = acc[mi][ni][half*2+0] + b0v;
                float oy = acc[mi][ni][half*2+1] + b1v;
                size_t off = (((size_t)(b*NH+h))*NT + tt)*NHD + d;
                if (mat==0)      { float2 o; o.x=ox; o.y=oy; *(float2*)&g_q[off] = o; }
                else if (mat==1) { float2 o; o.x=ox; o.y=oy; *(float2*)&g_k[off] = o; }
                else             { *(__half2*)&g_vh[off] = __floats2half2_rn(ox, oy); }
            }
        }
    }
}

// ---------------- K5: four output GEMMs, tf32 mma (fp16 A) --------------------
__global__ __launch_bounds__(256) void k_gemm4_mma(const float* __restrict__ Wfh, const float* __restrict__ bfh,
                                                   const float* __restrict__ Wfg, const float* __restrict__ bfg,
                                                   const float* __restrict__ Wrh, const float* __restrict__ brh,
                                                   const float* __restrict__ Wrg, const float* __restrict__ brg)
{
    __shared__ float sA[128][PA];
    __shared__ float sB[32][PB];
    const int tid = threadIdx.x, lane = tid&31, warp = tid>>5;
    const int g = lane>>2, t = lane&3;
    const int wm = warp>>2, wn = warp&3;
    const int n0 = blockIdx.x*128, m0 = blockIdx.y*128, mat = blockIdx.z;
    const __half* A   = (mat<2)? g_Tf : g_Tr;
    const float* W    = (mat==0)?Wfh:(mat==1)?Wfg:(mat==2)?Wrh:Wrg;
    const float* bias = (mat==0)?bfh:(mat==1)?bfg:(mat==2)?brh:brg;
    float* C = g_FG + (size_t)mat*NM*NHDIM;

    float acc[4][4][4];
#pragma unroll
    for (int mi=0;mi<4;mi++)
#pragma unroll
        for (int ni=0;ni<4;ni++)
#pragma unroll
            for (int r=0;r<4;r++) acc[mi][ni][r]=0.f;

    mma_mainloop_h(A, m0, W, n0, sA, sB, acc, tid, g, t, wm, wn);

#pragma unroll
    for (int mi=0;mi<4;mi++){
#pragma unroll
        for (int ni=0;ni<4;ni++){
            int colb = n0 + wn*32 + ni*8 + 2*t;
            float b0v = bias[colb], b1v = bias[colb+1];
            int r0 = m0 + wm*64 + mi*16 + g;
#pragma unroll
            for (int half=0; half<2; half++){
                int m = r0 + half*8;
                float2 o;
                o.x = acc[mi][ni][half*2+0] + b0v;
                o.y = acc[mi][ni][half*2+1] + b1v;
                *(float2*)&C[(size_t)m*NHDIM + colb] = o;
            }
        }
    }
}

// ---------------- K2: scores via tf32 mma -> fp16 S ---------------------------
__global__ __launch_bounds__(256) void k_scores_mma()
{
    __shared__ float sQ[128][PA];
    __shared__ float sK[128][PA];
    const int tid = threadIdx.x, lane = tid&31, warp = tid>>5;
    const int g = lane>>2, t = lane&3;
    const int wm = warp>>2, wn = warp&3;
    const int k0 = blockIdx.x*128, q0 = blockIdx.y*128;
    const size_t bh = blockIdx.z;
    const float* Q  = g_q + (bh*NT + (size_t)q0)*NHD;
    const float* Kp = g_k + (bh*NT + (size_t)k0)*NHD;
    __half* S = g_S + bh*NT*NT + (size_t)q0*NT + k0;

    float acc[4][4][4];
#pragma unroll
    for (int mi=0;mi<4;mi++)
#pragma unroll
        for (int ni=0;ni<4;ni++)
#pragma unroll
            for (int r=0;r<4;r++) acc[mi][ni][r]=0.f;

#pragma unroll
    for (int c=0; c<2; c++){
#pragma unroll
        for (int i=0;i<4;i++){
            int f = i*256 + tid;
            int r = f>>3, c4 = f&7;
            float4 a = *(const float4*)&Q [(size_t)r*NHD + c*32 + c4*4];
            float4 b = *(const float4*)&Kp[(size_t)r*NHD + c*32 + c4*4];
            uint32_t* pq = (uint32_t*)&sQ[r][c4*4];
            pq[0]=f2tf(a.x*0.125f); pq[1]=f2tf(a.y*0.125f);
            pq[2]=f2tf(a.z*0.125f); pq[3]=f2tf(a.w*0.125f);
            uint32_t* pk = (uint32_t*)&sK[r][c4*4];
            pk[0]=f2tf(b.x); pk[1]=f2tf(b.y); pk[2]=f2tf(b.z); pk[3]=f2tf(b.w);
        }
        __syncthreads();
#pragma unroll
        for (int kk=0; kk<4; kk++){
            const int k8 = kk*8;
            uint32_t afr[4][4];
#pragma unroll
            for (int mi=0; mi<4; mi++){
                int rb = wm*64 + mi*16;
                afr[mi][0] = __float_as_uint(sQ[rb+g  ][k8+t  ]);
                afr[mi][1] = __float_as_uint(sQ[rb+g+8][k8+t  ]);
                afr[mi][2] = __float_as_uint(sQ[rb+g  ][k8+t+4]);
                afr[mi][3] = __float_as_uint(sQ[rb+g+8][k8+t+4]);
            }
            uint32_t bfr[4][2];
#pragma unroll
            for (int ni=0; ni<4; ni++){
                int nb = wn*32 + ni*8 + g;
                bfr[ni][0] = __float_as_uint(sK[nb][k8+t  ]);
                bfr[ni][1] = __float_as_uint(sK[nb][k8+t+4]);
            }
#pragma unroll
            for (int mi=0; mi<4; mi++)
#pragma unroll
                for (int ni=0; ni<4; ni++)
                    mma_tf32(acc[mi][ni], afr[mi], bfr[ni]);
        }
        __syncthreads();
    }
#pragma unroll
    for (int mi=0;mi<4;mi++){
#pragma unroll
        for (int ni=0;ni<4;ni++){
            int col = wn*32 + ni*8 + 2*t;
            int r0 = wm*64 + mi*16 + g;
#pragma unroll
            for (int half=0; half<2; half++){
                *(__half2*)&S[(size_t)(r0+half*8)*NT + col] =
                    __floats2half2_rn(acc[mi][ni][half*2+0], acc[mi][ni][half*2+1]);
            }
        }
    }
}

// ------------- K3: softmax + gate + masks -> fp16 Pf/Pr ----------------------
__global__ __launch_bounds__(256) void k_gate(const float* __restrict__ cw,
                                              const float* __restrict__ cbp)
{
    __shared__ float sS[8][1024];
    __shared__ float sInv[8];
    __shared__ float red[8][16];
    __shared__ float sIf[8], sIr[8];
    const int tid = threadIdx.x;
    const int q = blockIdx.x, b = blockIdx.y;
    const size_t base = ((size_t)(b*NH))*NT*NT + (size_t)q*NT;

    // load all 8 head-rows (fp16 -> fp32)
#pragma unroll
    for (int i=0;i<4;i++){
        int f = i*256 + tid;           // 0..1023
        int h = f>>7, j8 = (f&127)*8;
        uint4 v = *(const uint4*)&g_S[base + (size_t)h*NT*NT + j8];
        const __half2* hv = (const __half2*)&v;
        float2 f0=__half22float2(hv[0]), f1=__half22float2(hv[1]);
        float2 f2=__half22float2(hv[2]), f3=__half22float2(hv[3]);
        sS[h][j8+0]=f0.x; sS[h][j8+1]=f0.y; sS[h][j8+2]=f1.x; sS[h][j8+3]=f1.y;
        sS[h][j8+4]=f2.x; sS[h][j8+5]=f2.y; sS[h][j8+6]=f3.x; sS[h][j8+7]=f3.y;
    }
    __syncthreads();

    const int warp = tid>>5, lane = tid&31;
    {
        float m = -1e30f;
#pragma unroll
        for (int j=0;j<32;j++) m = fmaxf(m, sS[warp][lane + 32*j]);
#pragma unroll
        for (int off=16; off>0; off>>=1) m = fmaxf(m, __shfl_xor_sync(0xffffffffu, m, off));
        float sum = 0.f;
#pragma unroll
        for (int j=0;j<32;j++){
            float e = __expf(sS[warp][lane + 32*j] - m);
            sS[warp][lane + 32*j] = e;
            sum += e;
        }
#pragma unroll
        for (int off=16; off>0; off>>=1) sum += __shfl_xor_sync(0xffffffffu, sum, off);
        if (lane==0) sInv[warp] = 1.0f/sum;
    }
    __syncthreads();

    float w[NH];
#pragma unroll
    for (int h=0;h<NH;h++) w[h]=cw[h];
    const float cb = cbp[0];
    float inv[NH];
#pragma unroll
    for (int h=0;h<NH;h++) inv[h]=sInv[h];

    float denf[NH], denr[NH];
#pragma unroll
    for (int h=0;h<NH;h++){ denf[h]=0.f; denr[h]=0.f; }
    float linv[2][2];

    // pass 1: A_t, lin, E=exp(A_t) back into sS, masked denominators
#pragma unroll
    for (int kk=0; kk<2; kk++){
#pragma unroll
        for (int j=0; j<2; j++){
            int k = kk*512 + tid*2 + j;
            float A[NH];
            float lin = cb;
#pragma unroll
            for (int h=0;h<NH;h++){ A[h] = sS[h][k]*inv[h]; lin = fmaf(w[h], A[h], lin); }
            linv[kk][j] = lin;
            bool bf = (lin <= 0.f);
            bool br = (lin >= 0.f);
#pragma unroll
            for (int h=0;h<NH;h++){
                float E = __expf(A[h]);
                sS[h][k] = E;
                denf[h] += bf ? E : 1.0f;
                denr[h] += br ? E : 1.0f;
            }
        }
    }
    // block reduction of 16 values
#pragma unroll
    for (int v=0; v<16; v++){
        float val = (v<8)? denf[v] : denr[v-8];
#pragma unroll
        for (int off=16; off>0; off>>=1) val += __shfl_down_sync(0xffffffffu, val, off);
        if (lane==0) red[warp][v]=val;
    }
    __syncthreads();
    if (tid < 16){
        float s=0.f;
#pragma unroll
        for (int wp=0; wp<8; wp++) s += red[wp][tid];
        float is = 1.0f/s;
        if (tid < 8) sIf[tid] = is;
        else         sIr[tid-8] = is;
    }
    __syncthreads();

    // pass 2: emit fp16 Pf/Pr (coalesced half2 stores)
#pragma unroll
    for (int kk=0; kk<2; kk++){
        int k = kk*512 + tid*2;
        float lin0 = linv[kk][0], lin1 = linv[kk][1];
        bool bf0 = (lin0 <= 0.f), bf1 = (lin1 <= 0.f);
        bool br0 = (lin0 >= 0.f), br1 = (lin1 >= 0.f);
#pragma unroll
        for (int h=0;h<NH;h++){
            float E0 = sS[h][k], E1 = sS[h][k+1];
            float fi = sIf[h], ri = sIr[h];
            __half2 pf = __floats2half2_rn((bf0? E0 : 1.0f)*fi, (bf1? E1 : 1.0f)*fi);
            __half2 pr = __floats2half2_rn((br0? E0 : 1.0f)*ri, (br1? E1 : 1.0f)*ri);
            size_t o = base + (size_t)h*NT*NT + k;
            *(__half2*)&g_Pf[o] = pf;
            *(__half2*)&g_Pr[o] = pr;
        }
    }
}

// ------------- K4: PV fp16 mma, q-tile 64, double-buffered --------------------
__global__ __launch_bounds__(256) void k_pv_mma()
{
    __shared__ __half sA[2][128*PH];   // rows 0-63 Pf, 64-127 Pr
    __shared__ __half sB[64*PH];       // V^T [d][k]
    const int tid = threadIdx.x, lane = tid&31, warp = tid>>5;
    const int g = lane>>2, t = lane&3;
    const int wm = warp>>1, wn = warp&1;       // wm: 4x32 rows, wn: 2x32 d-cols
    const int qt=blockIdx.x, h=blockIdx.y, b=blockIdx.z;
    const int q0 = qt*64;
    const size_t bh = (size_t)(b*NH+h);
    const __half* Pf = g_Pf + (bh*NT + (size_t)q0)*NT;
    const __half* Pr = g_Pr + (bh*NT + (size_t)q0)*NT;
    const __half* Vh = g_vh + bh*NT*NHD;

    const int qq = tid>>2, k8 = tid&3;        // A-copy coords (1 row per P mat)
    const int kl = tid>>3, d8 = tid&7;        // B-copy coords

    uint4 rA0, rA1, rB;
#define PV_LOAD(c) do { int k0c=(c)*32;                                          \
        rA0 = *(const uint4*)&Pf[(size_t)qq*NT + k0c + k8*8];                    \
        rA1 = *(const uint4*)&Pr[(size_t)qq*NT + k0c + k8*8];                    \
        rB  = *(const uint4*)&Vh[(size_t)(k0c+kl)*NHD + d8*8];                   \
    } while(0)
#define PV_STORE_A(bf) do { __half* Ap = sA[bf];                                 \
        *(uint4*)&Ap[(qq     )*PH + k8*8] = rA0;                                 \
        *(uint4*)&Ap[(qq + 64)*PH + k8*8] = rA1;                                 \
    } while(0)
#define PV_STORE_B() do { const __half* hh=(const __half*)&rB;                   \
        _Pragma("unroll")                                                        \
        for (int j=0;j<8;j++) sB[(d8*8+j)*PH + kl] = hh[j];                      \
    } while(0)

    float acc[2][4][4];
#pragma unroll
    for (int mi=0;mi<2;mi++)
#pragma unroll
        for (int ni=0;ni<4;ni++)
#pragma unroll
            for (int r=0;r<4;r++) acc[mi][ni][r]=0.f;

    PV_LOAD(0); PV_STORE_A(0); PV_STORE_B();
    __syncthreads();

    for (int c=0; c<32; c++){
        if (c<31) PV_LOAD(c+1);
        const __half* Ap = sA[c&1];
#pragma unroll
        for (int kk=0; kk<2; kk++){
            const int k16 = kk*16;
            uint32_t afr[2][4];
#pragma unroll
            for (int mi=0; mi<2; mi++){
                int rr = wm*32 + mi*16;
                afr[mi][0] = *(const uint32_t*)&Ap[(rr+g  )*PH + k16 + 2*t    ];
                afr[mi][1] = *(const uint32_t*)&Ap[(rr+g+8)*PH + k16 + 2*t    ];
                afr[mi][2] = *(const uint32_t*)&Ap[(rr+g  )*PH + k16 + 2*t + 8];
                afr[mi][3] = *(const uint32_t*)&Ap[(rr+g+8)*PH + k16 + 2*t + 8];
            }
            uint32_t bfr[4][2];
#pragma unroll
            for (int ni=0; ni<4; ni++){
                int nb = wn*32 + ni*8 + g;
                bfr[ni][0] = *(const uint32_t*)&sB[nb*PH + k16 + 2*t    ];
                bfr[ni][1] = *(const uint32_t*)&sB[nb*PH + k16 + 2*t + 8];
            }
#pragma unroll
            for (int mi=0; mi<2; mi++)
#pragma unroll
                for (int ni=0; ni<4; ni++)
                    mma_f16(acc[mi][ni], afr[mi], bfr[ni]);
        }
        if (c<31){
            PV_STORE_A((c+1)&1);
            __syncthreads();
            PV_STORE_B();
            __syncthreads();
        }
    }

    // epilogue: rows <64 -> g_Tf, rows >=64 -> g_Tr (fp16 stores)
#pragma unroll
    for (int mi=0;mi<2;mi++){
#pragma unroll
        for (int ni=0;ni<4;ni++){
            int col = wn*32 + ni*8 + 2*t;
            int r0 = wm*32 + mi*16 + g;
#pragma unroll
            for (int half=0; half<2; half++){
                int rr = r0 + half*8;
                __half* dst = (rr < 64) ? g_Tf : g_Tr;
                int q = q0 + (rr & 63);
                *(__half2*)&dst[((size_t)b*NT + q)*NHDIM + h*NHD + col] =
                    __floats2half2_rn(acc[mi][ni][half*2+0], acc[mi][ni][half*2+1]);
            }
        }
    }
#undef PV_LOAD
#undef PV_STORE_A
#undef PV_STORE_B
}

// ------------- K6: elementwise gate fuse -------------------------------------
__global__ __launch_bounds__(256) void k_fuse(float* __restrict__ out)
{
    const size_t idx = ((size_t)blockIdx.x*256 + threadIdx.x)*4;
    const size_t n = (size_t)NM*NHDIM;
    float4 Ff = *(const float4*)&g_FG[0*n + idx];
    float4 Gf = *(const float4*)&g_FG[1*n + idx];
    float4 Fr = *(const float4*)&g_FG[2*n + idx];
    float4 Gr = *(const float4*)&g_FG[3*n + idx];
    float4 o;
    {
        float gf = 1.f/(1.f + __expf(-Gf.x)), gr = 1.f/(1.f + __expf(-Gr.x));
        float wv = 1.f/(1.f + __expf(-(gf - gr)));
        o.x = Ff.x*wv + Fr.x*(1.f - wv);
    }
    {
        float gf = 1.f/(1.f + __expf(-Gf.y)), gr = 1.f/(1.f + __expf(-Gr.y));
        float wv = 1.f/(1.f + __expf(-(gf - gr)));
        o.y = Ff.y*wv + Fr.y*(1.f - wv);
    }
    {
        float gf = 1.f/(1.f + __expf(-Gf.z)), gr = 1.f/(1.f + __expf(-Gr.z));
        float wv = 1.f/(1.f + __expf(-(gf - gr)));
        o.z = Ff.z*wv + Fr.z*(1.f - wv);
    }
    {
        float gf = 1.f/(1.f + __expf(-Gf.w)), gr = 1.f/(1.f + __expf(-Gr.w));
        float wv = 1.f/(1.f + __expf(-(gf - gr)));
        o.w = Ff.w*wv + Fr.w*(1.f - wv);
    }
    *(float4*)&out[idx] = o;
}

// -------------------------------- launch --------------------------------------
extern "C" void kernel_launch(void* const* d_in, const int* in_sizes, int n_in,
                              void* d_out, int out_size)
{
    const float* x   = (const float*)d_in[0];
    const float* Wq  = (const float*)d_in[1];
    const float* bq  = (const float*)d_in[2];
    const float* Wk  = (const float*)d_in[3];
    const float* bk  = (const float*)d_in[4];
    const float* Wv  = (const float*)d_in[5];
    const float* bv  = (const float*)d_in[6];
    const float* cw  = (const float*)d_in[7];
    const float* cb  = (const float*)d_in[8];
    const float* Wfh = (const float*)d_in[9];
    const float* bfh = (const float*)d_in[10];
    const float* Wfg = (const float*)d_in[11];
    const float* bfg = (const float*)d_in[12];
    const float* Wrh = (const float*)d_in[13];
    const float* brh = (const float*)d_in[14];
    const float* Wrg = (const float*)d_in[15];
    const float* brg = (const float*)d_in[16];
    float* out = (float*)d_out;

    k_proj_mma  <<<dim3(12, 32), 256>>>(x, Wq, bq, Wk, bk, Wv, bv);
    k_scores_mma<<<dim3(8, 8, 32), 256>>>();
    k_gate      <<<dim3(1024, 4), 256>>>(cw, cb);
    k_pv_mma    <<<dim3(16, 8, 4), 256>>>();
    k_gemm4_mma <<<dim3(4, 32, 4), 256>>>(Wfh, bfh, Wfg, bfg, Wrh, brh, Wrg, brg);
    k_fuse      <<<2048, 256>>>(out);
}